// round 7
// baseline (speedup 1.0000x reference)
#include <cuda_runtime.h>
#include <cstdint>

#define D_MODEL 1024
#define SEQLEN  2048
#define BATCH   4
#define NHEADS  16
#define HDIM    64
#define MROWS   (BATCH * SEQLEN)   /* 8192 */
#define INV_TAU (1.0f / 0.07f)

// ---------------- scratch (__device__ globals; no allocs allowed) ----------
__device__ float    g_Qp[MROWS * D_MODEL];          // Q projection (fp32, pre-norm)
__device__ float    g_Kp[MROWS * D_MODEL];          // K projection (fp32, pre-norm)
__device__ uint32_t g_vt[MROWS * D_MODEL];          // V projection (tf32 u32)
// bf16 hi/lo packed k-pair arrays, layout [row][512]
__device__ uint32_t g_qh[MROWS * D_MODEL / 2], g_ql[MROWS * D_MODEL / 2];
__device__ uint32_t g_kh[MROWS * D_MODEL / 2], g_kl[MROWS * D_MODEL / 2];
__device__ uint32_t g_ah[MROWS * D_MODEL / 2], g_al[MROWS * D_MODEL / 2];
__device__ uint32_t g_wqh[D_MODEL * D_MODEL / 2], g_wql[D_MODEL * D_MODEL / 2];
__device__ uint32_t g_wkh[D_MODEL * D_MODEL / 2], g_wkl[D_MODEL * D_MODEL / 2];
__device__ uint32_t g_wvh[D_MODEL * D_MODEL / 2], g_wvl[D_MODEL * D_MODEL / 2];
__device__ uint32_t g_woh[D_MODEL * D_MODEL / 2], g_wol[D_MODEL * D_MODEL / 2];

// ---------------- helpers --------------------------------------------------
__device__ __forceinline__ uint32_t f2tf32(float f) {
    uint32_t r; asm("cvt.rna.tf32.f32 %0, %1;" : "=r"(r) : "f"(f)); return r;
}
__device__ __forceinline__ void mma8(float* c, const uint32_t* a, const uint32_t* b) {
    asm volatile("mma.sync.aligned.m16n8k8.row.col.f32.tf32.tf32.f32 "
        "{%0,%1,%2,%3},{%4,%5,%6,%7},{%8,%9},{%0,%1,%2,%3};"
        : "+f"(c[0]), "+f"(c[1]), "+f"(c[2]), "+f"(c[3])
        : "r"(a[0]), "r"(a[1]), "r"(a[2]), "r"(a[3]), "r"(b[0]), "r"(b[1]));
}
__device__ __forceinline__ void mma16(float* c, const uint32_t* a, const uint32_t* b) {
    asm volatile("mma.sync.aligned.m16n8k16.row.col.f32.bf16.bf16.f32 "
        "{%0,%1,%2,%3},{%4,%5,%6,%7},{%8,%9},{%0,%1,%2,%3};"
        : "+f"(c[0]), "+f"(c[1]), "+f"(c[2]), "+f"(c[3])
        : "r"(a[0]), "r"(a[1]), "r"(a[2]), "r"(a[3]), "r"(b[0]), "r"(b[1]));
}
__device__ __forceinline__ uint32_t hipack(float e, float o) {
    return __byte_perm(__float_as_uint(e), __float_as_uint(o), 0x7632);
}
__device__ __forceinline__ uint32_t lopack(float e, float o) {
    uint32_t r; asm("cvt.rn.bf16x2.f32 %0, %1, %2;" : "=r"(r) : "f"(o), "f"(e));
    return r;
}
__device__ __forceinline__ float truncbf(float x) {
    return __uint_as_float(__float_as_uint(x) & 0xffff0000u);
}
__device__ __forceinline__ void split2(float e, float o, uint32_t& h, uint32_t& l) {
    h = hipack(e, o);
    l = lopack(e - truncbf(e), o - truncbf(o));
}

// ---------------------------------------------------------------------------
// split_kernel: f32 -> bf16 hi/lo packed pair arrays ([row][512] layout)
// ---------------------------------------------------------------------------
__global__ __launch_bounds__(256) void split_kernel(
    const float* __restrict__ X, uint32_t* __restrict__ Hi,
    uint32_t* __restrict__ Lo, int n4)
{
    int i = blockIdx.x * blockDim.x + threadIdx.x;
    if (i >= n4) return;
    float4 v = ((const float4*)X)[i];
    uint32_t h0, l0, h1, l1;
    split2(v.x, v.y, h0, l0);
    split2(v.z, v.w, h1, l1);
    ((uint2*)Hi)[i] = make_uint2(h0, h1);
    ((uint2*)Lo)[i] = make_uint2(l0, l1);
}

// ---------------------------------------------------------------------------
// HMMA GEMM: C[M,N] = (Ahi+Alo) @ (Bhi+Blo)^T + bias  (hh+hl+lh)
// Block 128x128, BK=16, 256 threads (8 warps 2x4), warp tile 64x32.
// Smem fragment-ordered: A-frag = 1 LDS.128/tile, B-frag = 1 LDS.64/tile.
// OUTMODE 0: fp32 out.  OUTMODE 1: tf32 u32 out.
// ---------------------------------------------------------------------------
template<int OUTMODE>
__global__ __launch_bounds__(256) void gemm_hmma(
    const uint32_t* __restrict__ Ahi, const uint32_t* __restrict__ Alo,
    const uint32_t* __restrict__ Bhi, const uint32_t* __restrict__ Blo,
    const float* __restrict__ bias, void* __restrict__ Cout)
{
    __shared__ __align__(16) uint32_t AH[2][1024];
    __shared__ __align__(16) uint32_t AL[2][1024];
    __shared__ __align__(16) uint32_t BH[2][1024];
    __shared__ __align__(16) uint32_t BL[2][1024];

    const int t    = threadIdx.x;
    const int lane = t & 31, wid = t >> 5;
    const int wm   = wid >> 2, wn = wid & 3;
    const int brow = blockIdx.y * 128, bcol = blockIdx.x * 128;

    const int lrow = t >> 1;             // 0..127
    const int kph  = (t & 1) * 4;        // k-pair half: 0 or 4
    // fragment-ordered store bases (stride-16 for A, stride-2x4.. see map)
    const int aC0 = (lrow >> 4) * 128 + (lrow & 7) * 16 + ((lrow >> 3) & 1) + (kph >> 1);
    const int bC0 = (lrow >> 3) * 64 + (lrow & 7) * 8 + (kph >> 2);

    const uint32_t* gAh = Ahi + (size_t)(brow + lrow) * 512 + kph;
    const uint32_t* gAl = Alo + (size_t)(brow + lrow) * 512 + kph;
    const uint32_t* gBh = Bhi + (size_t)(bcol + lrow) * 512 + kph;
    const uint32_t* gBl = Blo + (size_t)(bcol + lrow) * 512 + kph;

    float acc[4][4][4];
#pragma unroll
    for (int mt = 0; mt < 4; mt++)
#pragma unroll
        for (int nt = 0; nt < 4; nt++)
#pragma unroll
            for (int i = 0; i < 4; i++) acc[mt][nt][i] = 0.f;

    uint4 pah = *(const uint4*)gAh;
    uint4 pal = *(const uint4*)gAl;
    uint4 pbh = *(const uint4*)gBh;
    uint4 pbl = *(const uint4*)gBl;

    // store chunk 0 into stage 0
#pragma unroll
    for (int k = 0; k < 4; k++) {
        AH[0][aC0 + k * 4] = (&pah.x)[k];
        AL[0][aC0 + k * 4] = (&pal.x)[k];
        BH[0][bC0 + k * 2] = (&pbh.x)[k];
        BL[0][bC0 + k * 2] = (&pbl.x)[k];
    }
    __syncthreads();

    for (int c = 0; c < 64; c++) {
        const int s = c & 1;
        if (c < 63) {
            pah = *(const uint4*)(gAh + (c + 1) * 8);
            pal = *(const uint4*)(gAl + (c + 1) * 8);
            pbh = *(const uint4*)(gBh + (c + 1) * 8);
            pbl = *(const uint4*)(gBl + (c + 1) * 8);
        }
        // fragments
        uint4 ahf[4], alf[4];
        uint2 bhf[4], blf[4];
#pragma unroll
        for (int mt = 0; mt < 4; mt++) {
            ahf[mt] = *(const uint4*)&AH[s][(wm * 4 + mt) * 128 + lane * 4];
            alf[mt] = *(const uint4*)&AL[s][(wm * 4 + mt) * 128 + lane * 4];
        }
#pragma unroll
        for (int nt = 0; nt < 4; nt++) {
            bhf[nt] = *(const uint2*)&BH[s][(wn * 4 + nt) * 64 + lane * 2];
            blf[nt] = *(const uint2*)&BL[s][(wn * 4 + nt) * 64 + lane * 2];
        }
#pragma unroll
        for (int mt = 0; mt < 4; mt++)
#pragma unroll
            for (int nt = 0; nt < 4; nt++) {
                mma16(acc[mt][nt], &ahf[mt].x, &bhf[nt].x);
                mma16(acc[mt][nt], &ahf[mt].x, &blf[nt].x);
                mma16(acc[mt][nt], &alf[mt].x, &bhf[nt].x);
            }
        if (c < 63) {
            const int s2 = s ^ 1;
#pragma unroll
            for (int k = 0; k < 4; k++) {
                AH[s2][aC0 + k * 4] = (&pah.x)[k];
                AL[s2][aC0 + k * 4] = (&pal.x)[k];
                BH[s2][bC0 + k * 2] = (&pbh.x)[k];
                BL[s2][bC0 + k * 2] = (&pbl.x)[k];
            }
        }
        __syncthreads();
    }

#pragma unroll
    for (int mt = 0; mt < 4; mt++)
#pragma unroll
        for (int nt = 0; nt < 4; nt++) {
            int gr = brow + wm * 64 + mt * 16 + (lane >> 2);
            int gc = bcol + wn * 32 + nt * 8 + (lane & 3) * 2;
            float2 bb = *(const float2*)(bias + gc);
            float v0 = acc[mt][nt][0] + bb.x, v1 = acc[mt][nt][1] + bb.y;
            float v2 = acc[mt][nt][2] + bb.x, v3 = acc[mt][nt][3] + bb.y;
            if (OUTMODE == 0) {
                float* C = (float*)Cout;
                *(float2*)(C + (size_t)gr * D_MODEL + gc)       = make_float2(v0, v1);
                *(float2*)(C + (size_t)(gr + 8) * D_MODEL + gc) = make_float2(v2, v3);
            } else {
                uint32_t* C = (uint32_t*)Cout;
                *(uint2*)(C + (size_t)gr * D_MODEL + gc)       = make_uint2(f2tf32(v0), f2tf32(v1));
                *(uint2*)(C + (size_t)(gr + 8) * D_MODEL + gc) = make_uint2(f2tf32(v2), f2tf32(v3));
            }
        }
}

// ---------------------------------------------------------------------------
// Per-head L2 normalize + emit bf16 hi/lo split
// ---------------------------------------------------------------------------
__global__ __launch_bounds__(256) void l2n_split(
    const float* __restrict__ X, uint32_t* __restrict__ Hi,
    uint32_t* __restrict__ Lo, int nchunks)
{
    int gid  = blockIdx.x * blockDim.x + threadIdx.x;
    int warp = gid >> 5;
    int lane = gid & 31;
    if (warp >= nchunks) return;
    const float* p = X + (size_t)warp * 64 + lane * 2;
    float2 v = *(const float2*)p;
    float ss = v.x * v.x + v.y * v.y;
#pragma unroll
    for (int m = 16; m > 0; m >>= 1)
        ss += __shfl_xor_sync(0xffffffffu, ss, m);
    float inv = 1.0f / fmaxf(sqrtf(ss), 1e-12f);
    uint32_t h, l;
    split2(v.x * inv, v.y * inv, h, l);
    Hi[(size_t)warp * 32 + lane] = h;
    Lo[(size_t)warp * 32 + lane] = l;
}

// ---------------------------------------------------------------------------
// Flash attention. Grid (L/64, B*H), 128 threads (4 warps).
// QK^T: 3-pass split-bf16 (pre-split inputs).  PV: single-pass tf32 (pre-cvt V).
// All smem tiles fragment-ordered. Output written as hi/lo split.
// ---------------------------------------------------------------------------
__global__ __launch_bounds__(128) void attn_tc(
    const uint32_t* __restrict__ Qh, const uint32_t* __restrict__ Ql,
    const uint32_t* __restrict__ Kh, const uint32_t* __restrict__ Kl,
    const uint32_t* __restrict__ Vt,
    uint32_t* __restrict__ Oh, uint32_t* __restrict__ Ol)
{
    __shared__ __align__(16) uint32_t SM[6400];
    uint32_t* KH = SM;                 // [16 groups][64]  (4KB)
    uint32_t* KL = SM + 1024;
    uint32_t* VF = SM + 2048;          // [32 groups][64]  (8KB)
    float*    Ps = (float*)(SM + 4096);// [64][36] fp32    (9KB)

    const int t    = threadIdx.x;
    const int lane = t & 31, w = t >> 5;
    const int qt   = blockIdx.x;
    const int bh   = blockIdx.y;
    const int b    = bh >> 4, h = bh & 15;

    // ---- stage Q hi/lo (rows qt*64..+63, 32 u32 each) into SM temp ----
    {
        const uint32_t* qh_g = Qh + (size_t)(b * SEQLEN + qt * 64) * 512 + h * 32;
        const uint32_t* ql_g = Ql + (size_t)(b * SEQLEN + qt * 64) * 512 + h * 32;
#pragma unroll
        for (int i = 0; i < 4; i++) {
            int id = t + i * 128;          // 0..511
            int row = id >> 3, q4 = id & 7;
            *(uint4*)&SM[row * 36 + q4 * 4]        = *(const uint4*)(qh_g + (size_t)row * 512 + q4 * 4);
            *(uint4*)&SM[2304 + row * 36 + q4 * 4] = *(const uint4*)(ql_g + (size_t)row * 512 + q4 * 4);
        }
    }
    __syncthreads();

    uint32_t qhi[4][4], qlo[4][4];
    {
        int r = w * 16 + (lane >> 2);
#pragma unroll
        for (int g = 0; g < 4; g++) {
            int kp0 = g * 8 + (lane & 3);
#pragma unroll
            for (int u = 0; u < 4; u++) {
                int rr = (u & 1) ? r + 8 : r;
                int kp = (u & 2) ? kp0 + 4 : kp0;
                qhi[g][u] = SM[rr * 36 + kp];
                qlo[g][u] = SM[2304 + rr * 36 + kp];
            }
        }
    }
    __syncthreads();   // staging reads done; loop will overwrite SM

    float o[8][4];
#pragma unroll
    for (int n8 = 0; n8 < 8; n8++)
#pragma unroll
        for (int i = 0; i < 4; i++) o[n8][i] = 0.f;
    float m0 = -1e30f, m1 = -1e30f, l0 = 0.f, l1 = 0.f;

    const uint32_t* kh_b = Kh + (size_t)(b * SEQLEN) * 512 + h * 32;
    const uint32_t* kl_b = Kl + (size_t)(b * SEQLEN) * 512 + h * 32;
    const uint32_t* v_b  = Vt + (size_t)(b * SEQLEN) * 1024 + h * 64;

    for (int kt = 0; kt < SEQLEN / 32; kt++) {
        if (kt) __syncthreads();
        // ---- K hi/lo tiles (fragment-ordered) ----
#pragma unroll
        for (int i = 0; i < 2; i++) {
            int id = t + i * 128;          // 0..255
            int row = id >> 3, q4 = id & 7;
            uint4 vh4 = *(const uint4*)(kh_b + (size_t)(kt * 32 + row) * 512 + q4 * 4);
            uint4 vl4 = *(const uint4*)(kl_b + (size_t)(kt * 32 + row) * 512 + q4 * 4);
#pragma unroll
            for (int k = 0; k < 4; k++) {
                int kp = q4 * 4 + k;
                int g = kp >> 3, kpl = kp & 7;
                int idx = (((row >> 3) & 3) * 4 + g) * 64
                        + ((row & 7) * 4 + (kpl & 3)) * 2 + (kpl >> 2);
                KH[idx] = (&vh4.x)[k];
                KL[idx] = (&vl4.x)[k];
            }
        }
        // ---- V tile (tf32, fragment-ordered) ----
#pragma unroll
        for (int i = 0; i < 4; i++) {
            int id = t + i * 128;          // 0..511
            int row = id >> 4, q4 = id & 15;
            uint4 vv4 = *(const uint4*)(v_b + (size_t)(kt * 32 + row) * 1024 + q4 * 4);
#pragma unroll
            for (int k = 0; k < 4; k++) {
                int c = q4 * 4 + k;
                int idx = ((row >> 3) * 8 + (c >> 3)) * 64
                        + ((c & 7) * 4 + (row & 3)) * 2 + ((row >> 2) & 1);
                VF[idx] = (&vv4.x)[k];
            }
        }
        __syncthreads();

        // ---- S = Q @ K^T (hh + hl + lh) ----
        float s[4][4];
#pragma unroll
        for (int nt = 0; nt < 4; nt++)
#pragma unroll
            for (int i = 0; i < 4; i++) s[nt][i] = 0.f;

#pragma unroll
        for (int g = 0; g < 4; g++) {
            uint2 bhf[4], blf[4];
#pragma unroll
            for (int nt = 0; nt < 4; nt++) {
                int grp = nt * 4 + g;
                bhf[nt] = *(const uint2*)&KH[grp * 64 + lane * 2];
                blf[nt] = *(const uint2*)&KL[grp * 64 + lane * 2];
            }
#pragma unroll
            for (int nt = 0; nt < 4; nt++) {
                mma16(s[nt], qhi[g], &bhf[nt].x);
                mma16(s[nt], qhi[g], &blf[nt].x);
                mma16(s[nt], qlo[g], &bhf[nt].x);
            }
        }

        // ---- scale by 1/tau + online softmax ----
        float mx0 = -1e30f, mx1 = -1e30f;
#pragma unroll
        for (int nt = 0; nt < 4; nt++) {
            s[nt][0] *= INV_TAU; s[nt][1] *= INV_TAU;
            s[nt][2] *= INV_TAU; s[nt][3] *= INV_TAU;
            mx0 = fmaxf(mx0, fmaxf(s[nt][0], s[nt][1]));
            mx1 = fmaxf(mx1, fmaxf(s[nt][2], s[nt][3]));
        }
        mx0 = fmaxf(mx0, __shfl_xor_sync(0xffffffffu, mx0, 1));
        mx0 = fmaxf(mx0, __shfl_xor_sync(0xffffffffu, mx0, 2));
        mx1 = fmaxf(mx1, __shfl_xor_sync(0xffffffffu, mx1, 1));
        mx1 = fmaxf(mx1, __shfl_xor_sync(0xffffffffu, mx1, 2));
        float mn0 = fmaxf(m0, mx0), mn1 = fmaxf(m1, mx1);
        float sc0 = __expf(m0 - mn0), sc1 = __expf(m1 - mn1);
        float sum0 = 0.f, sum1 = 0.f;
#pragma unroll
        for (int nt = 0; nt < 4; nt++) {
            s[nt][0] = __expf(s[nt][0] - mn0);
            s[nt][1] = __expf(s[nt][1] - mn0);
            s[nt][2] = __expf(s[nt][2] - mn1);
            s[nt][3] = __expf(s[nt][3] - mn1);
            sum0 += s[nt][0] + s[nt][1];
            sum1 += s[nt][2] + s[nt][3];
        }
        sum0 += __shfl_xor_sync(0xffffffffu, sum0, 1);
        sum0 += __shfl_xor_sync(0xffffffffu, sum0, 2);
        sum1 += __shfl_xor_sync(0xffffffffu, sum1, 1);
        sum1 += __shfl_xor_sync(0xffffffffu, sum1, 2);
        l0 = l0 * sc0 + sum0;  m0 = mn0;
        l1 = l1 * sc1 + sum1;  m1 = mn1;
#pragma unroll
        for (int n8 = 0; n8 < 8; n8++) {
            o[n8][0] *= sc0; o[n8][1] *= sc0;
            o[n8][2] *= sc1; o[n8][3] *= sc1;
        }

        // ---- write P (warp-private rows), consume as tf32 A fragments ----
        {
            int r = w * 16 + (lane >> 2);
#pragma unroll
            for (int nt = 0; nt < 4; nt++) {
                int col = nt * 8 + (lane & 3) * 2;
                *(float2*)&Ps[r * 36 + col]       = make_float2(s[nt][0], s[nt][1]);
                *(float2*)&Ps[(r + 8) * 36 + col] = make_float2(s[nt][2], s[nt][3]);
            }
        }
        __syncwarp();

        // ---- O += P @ V (single-pass tf32) ----
#pragma unroll
        for (int k8 = 0; k8 < 4; k8++) {
            uint32_t pa[4];
            {
                int r = w * 16 + (lane >> 2);
                int c = (lane & 3) + k8 * 8;
                pa[0] = f2tf32(Ps[r * 36 + c]);
                pa[1] = f2tf32(Ps[(r + 8) * 36 + c]);
                pa[2] = f2tf32(Ps[r * 36 + c + 4]);
                pa[3] = f2tf32(Ps[(r + 8) * 36 + c + 4]);
            }
#pragma unroll
            for (int n8 = 0; n8 < 8; n8++) {
                uint2 bv = *(const uint2*)&VF[(k8 * 8 + n8) * 64 + lane * 2];
                mma8(o[n8], pa, &bv.x);
            }
        }
    }

    // ---- normalize + split + store hi/lo ----
    {
        float inv0 = 1.0f / l0, inv1 = 1.0f / l1;
        int r = b * SEQLEN + qt * 64 + w * 16 + (lane >> 2);
#pragma unroll
        for (int n8 = 0; n8 < 8; n8++) {
            size_t i0 = (size_t)r * 512 + h * 32 + n8 * 4 + (lane & 3);
            size_t i1 = i0 + 8 * 512;
            uint32_t hh, ll;
            split2(o[n8][0] * inv0, o[n8][1] * inv0, hh, ll);
            Oh[i0] = hh; Ol[i0] = ll;
            split2(o[n8][2] * inv1, o[n8][3] * inv1, hh, ll);
            Oh[i1] = hh; Ol[i1] = ll;
        }
    }
}

// ---------------------------------------------------------------------------
extern "C" void kernel_launch(void* const* d_in, const int* in_sizes, int n_in,
                              void* d_out, int out_size)
{
    const float* q  = (const float*)d_in[0];
    const float* k  = (const float*)d_in[1];
    const float* v  = (const float*)d_in[2];
    const float* Wq = (const float*)d_in[3];
    const float* bq = (const float*)d_in[4];
    const float* Wk = (const float*)d_in[5];
    const float* bk = (const float*)d_in[6];
    const float* Wv = (const float*)d_in[7];
    const float* bv = (const float*)d_in[8];
    const float* Wo = (const float*)d_in[9];
    const float* bo = (const float*)d_in[10];
    float* out = (float*)d_out;

    float *Qp, *Kp;
    uint32_t *vt, *qh, *ql, *kh, *kl, *ah, *al;
    uint32_t *wqh, *wql, *wkh, *wkl, *wvh, *wvl, *woh, *wol;
    cudaGetSymbolAddress((void**)&Qp, g_Qp);
    cudaGetSymbolAddress((void**)&Kp, g_Kp);
    cudaGetSymbolAddress((void**)&vt, g_vt);
    cudaGetSymbolAddress((void**)&qh, g_qh);  cudaGetSymbolAddress((void**)&ql, g_ql);
    cudaGetSymbolAddress((void**)&kh, g_kh);  cudaGetSymbolAddress((void**)&kl, g_kl);
    cudaGetSymbolAddress((void**)&ah, g_ah);  cudaGetSymbolAddress((void**)&al, g_al);
    cudaGetSymbolAddress((void**)&wqh, g_wqh); cudaGetSymbolAddress((void**)&wql, g_wql);
    cudaGetSymbolAddress((void**)&wkh, g_wkh); cudaGetSymbolAddress((void**)&wkl, g_wkl);
    cudaGetSymbolAddress((void**)&wvh, g_wvh); cudaGetSymbolAddress((void**)&wvl, g_wvl);
    cudaGetSymbolAddress((void**)&woh, g_woh); cudaGetSymbolAddress((void**)&wol, g_wol);

    const int nAct4 = MROWS * D_MODEL / 4;
    const int nW4   = D_MODEL * D_MODEL / 4;

    // input splits (v reuses ah/al; consumed before attention writes them)
    split_kernel<<<nAct4 / 256, 256>>>(q, qh, ql, nAct4);
    split_kernel<<<nAct4 / 256, 256>>>(k, kh, kl, nAct4);
    split_kernel<<<nAct4 / 256, 256>>>(v, ah, al, nAct4);
    split_kernel<<<nW4 / 256, 256>>>(Wq, wqh, wql, nW4);
    split_kernel<<<nW4 / 256, 256>>>(Wk, wkh, wkl, nW4);
    split_kernel<<<nW4 / 256, 256>>>(Wv, wvh, wvl, nW4);
    split_kernel<<<nW4 / 256, 256>>>(Wo, woh, wol, nW4);

    dim3 ggrid(D_MODEL / 128, MROWS / 128);   // (8, 64)
    gemm_hmma<0><<<ggrid, 256>>>(qh, ql, wqh, wql, bq, Qp);
    gemm_hmma<0><<<ggrid, 256>>>(kh, kl, wkh, wkl, bk, Kp);
    gemm_hmma<1><<<ggrid, 256>>>(ah, al, wvh, wvl, bv, vt);

    const int nchunks = MROWS * NHEADS;       // 131072
    l2n_split<<<nchunks / 8, 256>>>(Qp, qh, ql, nchunks);
    l2n_split<<<nchunks / 8, 256>>>(Kp, kh, kl, nchunks);

    attn_tc<<<dim3(SEQLEN / 64, BATCH * NHEADS), 128>>>(qh, ql, kh, kl, vt, ah, al);

    gemm_hmma<0><<<ggrid, 256>>>(ah, al, woh, wol, bo, out);
}

// round 8
// speedup vs baseline: 1.2683x; 1.2683x over previous
#include <cuda_runtime.h>
#include <cstdint>

#define D_MODEL 1024
#define SEQLEN  2048
#define BATCH   4
#define NHEADS  16
#define HDIM    64
#define MROWS   (BATCH * SEQLEN)   /* 8192 */
#define INV_TAU (1.0f / 0.07f)

// ---------------- scratch (__device__ globals; no allocs allowed) ----------
__device__ float g_Qp[MROWS * D_MODEL];
__device__ float g_Kp[MROWS * D_MODEL];
__device__ float g_Vp[MROWS * D_MODEL];
__device__ float g_Ao[MROWS * D_MODEL];
// bf16 hi/lo packed k-pair arrays, [row][512] u32
__device__ uint32_t g_qh[MROWS * D_MODEL / 2], g_ql[MROWS * D_MODEL / 2];
__device__ uint32_t g_kh[MROWS * D_MODEL / 2], g_kl[MROWS * D_MODEL / 2];
__device__ uint32_t g_vh[MROWS * D_MODEL / 2], g_vl[MROWS * D_MODEL / 2];
__device__ uint32_t g_wqh[D_MODEL * D_MODEL / 2], g_wql[D_MODEL * D_MODEL / 2];
__device__ uint32_t g_wkh[D_MODEL * D_MODEL / 2], g_wkl[D_MODEL * D_MODEL / 2];
__device__ uint32_t g_wvh[D_MODEL * D_MODEL / 2], g_wvl[D_MODEL * D_MODEL / 2];
__device__ uint32_t g_woh[D_MODEL * D_MODEL / 2], g_wol[D_MODEL * D_MODEL / 2];

// ---------------- helpers --------------------------------------------------
__device__ __forceinline__ uint32_t f2tf32(float f) {
    uint32_t r; asm("cvt.rna.tf32.f32 %0, %1;" : "=r"(r) : "f"(f)); return r;
}
__device__ __forceinline__ void mma8(float* c, const uint32_t* a, const uint32_t* b) {
    asm volatile("mma.sync.aligned.m16n8k8.row.col.f32.tf32.tf32.f32 "
        "{%0,%1,%2,%3},{%4,%5,%6,%7},{%8,%9},{%0,%1,%2,%3};"
        : "+f"(c[0]), "+f"(c[1]), "+f"(c[2]), "+f"(c[3])
        : "r"(a[0]), "r"(a[1]), "r"(a[2]), "r"(a[3]), "r"(b[0]), "r"(b[1]));
}
__device__ __forceinline__ void mma16(float* c, const uint32_t* a, const uint32_t* b) {
    asm volatile("mma.sync.aligned.m16n8k16.row.col.f32.bf16.bf16.f32 "
        "{%0,%1,%2,%3},{%4,%5,%6,%7},{%8,%9},{%0,%1,%2,%3};"
        : "+f"(c[0]), "+f"(c[1]), "+f"(c[2]), "+f"(c[3])
        : "r"(a[0]), "r"(a[1]), "r"(a[2]), "r"(a[3]), "r"(b[0]), "r"(b[1]));
}
__device__ __forceinline__ uint32_t hipack(float e, float o) {
    return __byte_perm(__float_as_uint(e), __float_as_uint(o), 0x7632);
}
__device__ __forceinline__ uint32_t lopack(float e, float o) {
    uint32_t r; asm("cvt.rn.bf16x2.f32 %0, %1, %2;" : "=r"(r) : "f"(o), "f"(e));
    return r;
}
__device__ __forceinline__ float truncbf(float x) {
    return __uint_as_float(__float_as_uint(x) & 0xffff0000u);
}
__device__ __forceinline__ void split2(float e, float o, uint32_t& h, uint32_t& l) {
    h = hipack(e, o);
    l = lopack(e - truncbf(e), o - truncbf(o));
}

// ---------------------------------------------------------------------------
// split_kernel: f32 -> bf16 hi/lo packed pair arrays
// ---------------------------------------------------------------------------
__global__ __launch_bounds__(256) void split_kernel(
    const float* __restrict__ X, uint32_t* __restrict__ Hi,
    uint32_t* __restrict__ Lo, int n4)
{
    int i = blockIdx.x * blockDim.x + threadIdx.x;
    if (i >= n4) return;
    float4 v = ((const float4*)X)[i];
    uint32_t h0, l0, h1, l1;
    split2(v.x, v.y, h0, l0);
    split2(v.z, v.w, h1, l1);
    ((uint2*)Hi)[i] = make_uint2(h0, h1);
    ((uint2*)Lo)[i] = make_uint2(l0, l1);
}

// ---------------------------------------------------------------------------
// Split-bf16 GEMM (3-pass, pre-split inputs): C = A @ W^T + bias
// Block 128x128, BK=16, 256 threads (8 warps 2x4), warp tile 64x32.
// Smem u32 k-pairs, stride 12 (frag reads conflict-free, STS.128 aligned).
// ---------------------------------------------------------------------------
__global__ __launch_bounds__(256) void gemm_ps(
    const uint32_t* __restrict__ Ahi, const uint32_t* __restrict__ Alo,
    const uint32_t* __restrict__ Bhi, const uint32_t* __restrict__ Blo,
    const float* __restrict__ bias, float* __restrict__ C)
{
    const int N = D_MODEL;
    __shared__ __align__(16) uint32_t AH[128 * 12];
    __shared__ __align__(16) uint32_t AL[128 * 12];
    __shared__ __align__(16) uint32_t BH[128 * 12];
    __shared__ __align__(16) uint32_t BL[128 * 12];

    const int t    = threadIdx.x;
    const int lane = t & 31, wid = t >> 5;
    const int wm   = wid >> 2, wn = wid & 3;
    const int brow = blockIdx.y * 128, bcol = blockIdx.x * 128;
    const int lr   = t >> 1;            // 0..127
    const int lkp  = (t & 1) * 4;       // k-pair offset 0 or 4

    const uint32_t* gAh = Ahi + (size_t)(brow + lr) * 512 + lkp;
    const uint32_t* gAl = Alo + (size_t)(brow + lr) * 512 + lkp;
    const uint32_t* gBh = Bhi + (size_t)(bcol + lr) * 512 + lkp;
    const uint32_t* gBl = Blo + (size_t)(bcol + lr) * 512 + lkp;

    float acc[4][4][4];
#pragma unroll
    for (int mt = 0; mt < 4; mt++)
#pragma unroll
        for (int nt = 0; nt < 4; nt++)
#pragma unroll
            for (int i = 0; i < 4; i++) acc[mt][nt][i] = 0.f;

    uint4 pah = *(const uint4*)gAh;
    uint4 pal = *(const uint4*)gAl;
    uint4 pbh = *(const uint4*)gBh;
    uint4 pbl = *(const uint4*)gBl;

    const int sbi = lr * 12 + lkp;

    for (int c = 0; c < 64; c++) {
        __syncthreads();
        *(uint4*)&AH[sbi] = pah;
        *(uint4*)&AL[sbi] = pal;
        *(uint4*)&BH[sbi] = pbh;
        *(uint4*)&BL[sbi] = pbl;
        __syncthreads();
        if (c < 63) {
            pah = *(const uint4*)(gAh + (c + 1) * 8);
            pal = *(const uint4*)(gAl + (c + 1) * 8);
            pbh = *(const uint4*)(gBh + (c + 1) * 8);
            pbl = *(const uint4*)(gBl + (c + 1) * 8);
        }
        {
            const int kk = lane & 3;
            uint32_t ah[4][4], al[4][4], bh[4][2], bl[4][2];
#pragma unroll
            for (int mt = 0; mt < 4; mt++) {
                int r = wm * 64 + mt * 16 + (lane >> 2);
                ah[mt][0] = AH[r * 12 + kk];
                ah[mt][1] = AH[(r + 8) * 12 + kk];
                ah[mt][2] = AH[r * 12 + kk + 4];
                ah[mt][3] = AH[(r + 8) * 12 + kk + 4];
                al[mt][0] = AL[r * 12 + kk];
                al[mt][1] = AL[(r + 8) * 12 + kk];
                al[mt][2] = AL[r * 12 + kk + 4];
                al[mt][3] = AL[(r + 8) * 12 + kk + 4];
            }
#pragma unroll
            for (int nt = 0; nt < 4; nt++) {
                int n = wn * 32 + nt * 8 + (lane >> 2);
                bh[nt][0] = BH[n * 12 + kk];
                bh[nt][1] = BH[n * 12 + kk + 4];
                bl[nt][0] = BL[n * 12 + kk];
                bl[nt][1] = BL[n * 12 + kk + 4];
            }
#pragma unroll
            for (int mt = 0; mt < 4; mt++)
#pragma unroll
                for (int nt = 0; nt < 4; nt++) {
                    mma16(acc[mt][nt], ah[mt], bh[nt]);
                    mma16(acc[mt][nt], ah[mt], bl[nt]);
                    mma16(acc[mt][nt], al[mt], bh[nt]);
                }
        }
    }

#pragma unroll
    for (int mt = 0; mt < 4; mt++)
#pragma unroll
        for (int nt = 0; nt < 4; nt++) {
            int gr = brow + wm * 64 + mt * 16 + (lane >> 2);
            int gc = bcol + wn * 32 + nt * 8 + (lane & 3) * 2;
            float2 bb = *(const float2*)(bias + gc);
            float2 o0 = make_float2(acc[mt][nt][0] + bb.x, acc[mt][nt][1] + bb.y);
            float2 o1 = make_float2(acc[mt][nt][2] + bb.x, acc[mt][nt][3] + bb.y);
            *(float2*)(C + (size_t)gr * N + gc)       = o0;
            *(float2*)(C + (size_t)(gr + 8) * N + gc) = o1;
        }
}

// ---------------------------------------------------------------------------
// Per-head L2 normalize
// ---------------------------------------------------------------------------
__global__ __launch_bounds__(256) void l2norm_kernel(float* __restrict__ X, int nchunks)
{
    int gid  = blockIdx.x * blockDim.x + threadIdx.x;
    int warp = gid >> 5;
    int lane = gid & 31;
    if (warp >= nchunks) return;
    float* p = X + (size_t)warp * 64 + lane * 2;
    float2 v = *(float2*)p;
    float ss = v.x * v.x + v.y * v.y;
#pragma unroll
    for (int m = 16; m > 0; m >>= 1)
        ss += __shfl_xor_sync(0xffffffffu, ss, m);
    float inv = 1.0f / fmaxf(sqrtf(ss), 1e-12f);
    v.x *= inv; v.y *= inv;
    *(float2*)p = v;
}

// ---------------------------------------------------------------------------
// Flash attention (R5 structure; Khi/Klo stride 36 for conflict-free reads).
// Grid (L/64, B*H), 128 threads (4 warps).
// QK^T: 3-pass split-bf16 (k16).  PV: single-pass tf32 (k8).
// ---------------------------------------------------------------------------
__global__ __launch_bounds__(128) void attn_tc(
    const float* __restrict__ Q, const float* __restrict__ K,
    const float* __restrict__ V, float* __restrict__ O)
{
    __shared__ uint32_t KS[64 * 68];       // union: Q f32 staging | Khi+Klo
    __shared__ uint32_t Vs[32 * 72];       // V tf32
    __shared__ float    Ps[64 * 36];       // P f32

    uint32_t* Khi = KS;                    // [32][36] u32 k-pairs
    uint32_t* Klo = KS + 32 * 36;
    float*    KSf = (float*)KS;

    const int t    = threadIdx.x;
    const int lane = t & 31, w = t >> 5;
    const int qt   = blockIdx.x;
    const int bh   = blockIdx.y;
    const int b    = bh >> 4, h = bh & 15;
    const size_t base = (size_t)(b * SEQLEN) * D_MODEL + h * HDIM;

    // ---- stage Q (scaled by 1/tau) into KS as fp32 [64][68] ----
#pragma unroll
    for (int i = 0; i < 8; i++) {
        int id = t + i * 128;
        int row = id >> 4, c4 = id & 15;
        float4 v = *(const float4*)(Q + base + (size_t)(qt * 64 + row) * D_MODEL + c4 * 4);
        KSf[row * 68 + c4 * 4 + 0] = v.x * INV_TAU;
        KSf[row * 68 + c4 * 4 + 1] = v.y * INV_TAU;
        KSf[row * 68 + c4 * 4 + 2] = v.z * INV_TAU;
        KSf[row * 68 + c4 * 4 + 3] = v.w * INV_TAU;
    }
    __syncthreads();

    // ---- build Q hi/lo fragments (4 k16 groups) in registers ----
    uint32_t qhi[4][4], qlo[4][4];
    {
        int r = w * 16 + (lane >> 2);
#pragma unroll
        for (int g = 0; g < 4; g++) {
            int kp0 = g * 8 + (lane & 3);
#pragma unroll
            for (int u = 0; u < 4; u++) {
                int rr = (u & 1) ? r + 8 : r;
                int kp = (u & 2) ? kp0 + 4 : kp0;
                float e = KSf[rr * 68 + kp * 2];
                float o = KSf[rr * 68 + kp * 2 + 1];
                split2(e, o, qhi[g][u], qlo[g][u]);
            }
        }
    }
    __syncthreads();   // all Q frag reads done before Khi/Klo overwrite KS

    float o[8][4];
#pragma unroll
    for (int n8 = 0; n8 < 8; n8++)
#pragma unroll
        for (int i = 0; i < 4; i++) o[n8][i] = 0.f;
    float m0 = -1e30f, m1 = -1e30f, l0 = 0.f, l1 = 0.f;

    for (int kt = 0; kt < SEQLEN / 32; kt++) {
        if (kt) __syncthreads();
        // ---- load K (bf16 hi/lo) and V (tf32) tiles ----
#pragma unroll
        for (int i = 0; i < 4; i++) {
            int id = t + i * 128;
            int row = id >> 4, c4 = id & 15;
            float4 kv = *(const float4*)(K + base + (size_t)(kt * 32 + row) * D_MODEL + c4 * 4);
            float4 vv = *(const float4*)(V + base + (size_t)(kt * 32 + row) * D_MODEL + c4 * 4);
            int bi = row * 36 + c4 * 2;
            uint32_t hh, ll;
            split2(kv.x, kv.y, hh, ll); Khi[bi + 0] = hh; Klo[bi + 0] = ll;
            split2(kv.z, kv.w, hh, ll); Khi[bi + 1] = hh; Klo[bi + 1] = ll;
            int vi = row * 72 + c4 * 4;
            Vs[vi + 0] = f2tf32(vv.x);
            Vs[vi + 1] = f2tf32(vv.y);
            Vs[vi + 2] = f2tf32(vv.z);
            Vs[vi + 3] = f2tf32(vv.w);
        }
        __syncthreads();

        // ---- S = Q @ K^T (hh + hl + lh), 4 k16 groups ----
        float s[4][4];
#pragma unroll
        for (int nt = 0; nt < 4; nt++)
#pragma unroll
            for (int i = 0; i < 4; i++) s[nt][i] = 0.f;

#pragma unroll
        for (int g = 0; g < 4; g++) {
            int kp = g * 8 + (lane & 3);
            uint32_t bhf[4][2], blf[4][2];
#pragma unroll
            for (int nt = 0; nt < 4; nt++) {
                int n = nt * 8 + (lane >> 2);
                bhf[nt][0] = Khi[n * 36 + kp];
                bhf[nt][1] = Khi[n * 36 + kp + 4];
                blf[nt][0] = Klo[n * 36 + kp];
                blf[nt][1] = Klo[n * 36 + kp + 4];
            }
#pragma unroll
            for (int nt = 0; nt < 4; nt++) {
                mma16(s[nt], qhi[g], bhf[nt]);
                mma16(s[nt], qhi[g], blf[nt]);
                mma16(s[nt], qlo[g], bhf[nt]);
            }
        }

        // ---- online softmax (rows lane>>2 and +8) ----
        float mx0 = -1e30f, mx1 = -1e30f;
#pragma unroll
        for (int nt = 0; nt < 4; nt++) {
            mx0 = fmaxf(mx0, fmaxf(s[nt][0], s[nt][1]));
            mx1 = fmaxf(mx1, fmaxf(s[nt][2], s[nt][3]));
        }
        mx0 = fmaxf(mx0, __shfl_xor_sync(0xffffffffu, mx0, 1));
        mx0 = fmaxf(mx0, __shfl_xor_sync(0xffffffffu, mx0, 2));
        mx1 = fmaxf(mx1, __shfl_xor_sync(0xffffffffu, mx1, 1));
        mx1 = fmaxf(mx1, __shfl_xor_sync(0xffffffffu, mx1, 2));
        float mn0 = fmaxf(m0, mx0), mn1 = fmaxf(m1, mx1);
        float sc0 = __expf(m0 - mn0), sc1 = __expf(m1 - mn1);
        float sum0 = 0.f, sum1 = 0.f;
#pragma unroll
        for (int nt = 0; nt < 4; nt++) {
            s[nt][0] = __expf(s[nt][0] - mn0);
            s[nt][1] = __expf(s[nt][1] - mn0);
            s[nt][2] = __expf(s[nt][2] - mn1);
            s[nt][3] = __expf(s[nt][3] - mn1);
            sum0 += s[nt][0] + s[nt][1];
            sum1 += s[nt][2] + s[nt][3];
        }
        sum0 += __shfl_xor_sync(0xffffffffu, sum0, 1);
        sum0 += __shfl_xor_sync(0xffffffffu, sum0, 2);
        sum1 += __shfl_xor_sync(0xffffffffu, sum1, 1);
        sum1 += __shfl_xor_sync(0xffffffffu, sum1, 2);
        l0 = l0 * sc0 + sum0;  m0 = mn0;
        l1 = l1 * sc1 + sum1;  m1 = mn1;
#pragma unroll
        for (int n8 = 0; n8 < 8; n8++) {
            o[n8][0] *= sc0; o[n8][1] *= sc0;
            o[n8][2] *= sc1; o[n8][3] *= sc1;
        }

        // ---- write P (per-warp rows), consume as tf32 A fragments ----
        {
            int r = w * 16 + (lane >> 2);
#pragma unroll
            for (int nt = 0; nt < 4; nt++) {
                int col = nt * 8 + (lane & 3) * 2;
                *(float2*)&Ps[r * 36 + col]       = make_float2(s[nt][0], s[nt][1]);
                *(float2*)&Ps[(r + 8) * 36 + col] = make_float2(s[nt][2], s[nt][3]);
            }
        }
        __syncwarp();

        // ---- O += P @ V (single-pass tf32) ----
#pragma unroll
        for (int k8 = 0; k8 < 4; k8++) {
            uint32_t pa[4];
            {
                int r = w * 16 + (lane >> 2);
                int c = (lane & 3) + k8 * 8;
                pa[0] = f2tf32(Ps[r * 36 + c]);
                pa[1] = f2tf32(Ps[(r + 8) * 36 + c]);
                pa[2] = f2tf32(Ps[r * 36 + c + 4]);
                pa[3] = f2tf32(Ps[(r + 8) * 36 + c + 4]);
            }
#pragma unroll
            for (int n8 = 0; n8 < 8; n8++) {
                uint32_t bv[2];
                int kk = (lane & 3) + k8 * 8;
                int n  = (lane >> 2) + n8 * 8;
                bv[0] = Vs[kk * 72 + n];
                bv[1] = Vs[(kk + 4) * 72 + n];
                mma8(o[n8], pa, bv);
            }
        }
    }

    // ---- normalize + store ----
    {
        float inv0 = 1.0f / l0, inv1 = 1.0f / l1;
        int r = qt * 64 + w * 16 + (lane >> 2);
#pragma unroll
        for (int n8 = 0; n8 < 8; n8++) {
            int col = n8 * 8 + (lane & 3) * 2;
            *(float2*)(O + base + (size_t)r * D_MODEL + col) =
                make_float2(o[n8][0] * inv0, o[n8][1] * inv0);
            *(float2*)(O + base + (size_t)(r + 8) * D_MODEL + col) =
                make_float2(o[n8][2] * inv1, o[n8][3] * inv1);
        }
    }
}

// ---------------------------------------------------------------------------
extern "C" void kernel_launch(void* const* d_in, const int* in_sizes, int n_in,
                              void* d_out, int out_size)
{
    const float* q  = (const float*)d_in[0];
    const float* k  = (const float*)d_in[1];
    const float* v  = (const float*)d_in[2];
    const float* Wq = (const float*)d_in[3];
    const float* bq = (const float*)d_in[4];
    const float* Wk = (const float*)d_in[5];
    const float* bk = (const float*)d_in[6];
    const float* Wv = (const float*)d_in[7];
    const float* bv = (const float*)d_in[8];
    const float* Wo = (const float*)d_in[9];
    const float* bo = (const float*)d_in[10];
    float* out = (float*)d_out;

    float *Qp, *Kp, *Vp, *Ao;
    uint32_t *qh, *ql, *kh, *kl, *vh, *vl;
    uint32_t *wqh, *wql, *wkh, *wkl, *wvh, *wvl, *woh, *wol;
    cudaGetSymbolAddress((void**)&Qp, g_Qp);
    cudaGetSymbolAddress((void**)&Kp, g_Kp);
    cudaGetSymbolAddress((void**)&Vp, g_Vp);
    cudaGetSymbolAddress((void**)&Ao, g_Ao);
    cudaGetSymbolAddress((void**)&qh, g_qh);  cudaGetSymbolAddress((void**)&ql, g_ql);
    cudaGetSymbolAddress((void**)&kh, g_kh);  cudaGetSymbolAddress((void**)&kl, g_kl);
    cudaGetSymbolAddress((void**)&vh, g_vh);  cudaGetSymbolAddress((void**)&vl, g_vl);
    cudaGetSymbolAddress((void**)&wqh, g_wqh); cudaGetSymbolAddress((void**)&wql, g_wql);
    cudaGetSymbolAddress((void**)&wkh, g_wkh); cudaGetSymbolAddress((void**)&wkl, g_wkl);
    cudaGetSymbolAddress((void**)&wvh, g_wvh); cudaGetSymbolAddress((void**)&wvl, g_wvl);
    cudaGetSymbolAddress((void**)&woh, g_woh); cudaGetSymbolAddress((void**)&wol, g_wol);

    const int nAct4 = MROWS * D_MODEL / 4;
    const int nW4   = D_MODEL * D_MODEL / 4;

    split_kernel<<<nAct4 / 256, 256>>>(q, qh, ql, nAct4);
    split_kernel<<<nAct4 / 256, 256>>>(k, kh, kl, nAct4);
    split_kernel<<<nAct4 / 256, 256>>>(v, vh, vl, nAct4);
    split_kernel<<<nW4 / 256, 256>>>(Wq, wqh, wql, nW4);
    split_kernel<<<nW4 / 256, 256>>>(Wk, wkh, wkl, nW4);
    split_kernel<<<nW4 / 256, 256>>>(Wv, wvh, wvl, nW4);
    split_kernel<<<nW4 / 256, 256>>>(Wo, woh, wol, nW4);

    dim3 ggrid(D_MODEL / 128, MROWS / 128);   // (8, 64)
    gemm_ps<<<ggrid, 256>>>(qh, ql, wqh, wql, bq, Qp);
    gemm_ps<<<ggrid, 256>>>(kh, kl, wkh, wkl, bk, Kp);
    gemm_ps<<<ggrid, 256>>>(vh, vl, wvh, wvl, bv, Vp);

    const int nchunks = MROWS * NHEADS;       // 131072
    l2norm_kernel<<<nchunks / 8, 256>>>(Qp, nchunks);
    l2norm_kernel<<<nchunks / 8, 256>>>(Kp, nchunks);

    attn_tc<<<dim3(SEQLEN / 64, BATCH * NHEADS), 128>>>(Qp, Kp, Vp, Ao);

    // reuse qh/ql for the attention-output split
    split_kernel<<<nAct4 / 256, 256>>>(Ao, qh, ql, nAct4);
    gemm_ps<<<ggrid, 256>>>(qh, ql, woh, wol, bo, out);
}